// round 7
// baseline (speedup 1.0000x reference)
#include <cuda_runtime.h>
#include <cuda_bf16.h>

#define FULLMASK 0xffffffffu

__device__ float g_losses[256];

// One CTA = 256 threads = 8 warps = TWO batches:
//   warps 0-3 (one per SMSP) -> batch 2*bid, warps 4-7 -> batch 2*bid+1.
// Grid 128, occupancy 1 -> every SM holds exactly 2 warps per SMSP (tails
// mutually hidden), all 4 SMSPs busy.
// Thread owns ONE column c over the FULL i-range: 64 bf16x2 expT regs,
// 64 HFMA2 per step. One __syncthreads per step; e[0] free-normalizer rescale.
__global__ void __launch_bounds__(256, 1) k_crf_forward(
    const float* __restrict__ feats,   // [B,S,L]
    const float* __restrict__ startT,  // [L]
    const float* __restrict__ endT,    // [L]
    const float* __restrict__ trans,   // [L,L]
    const float* __restrict__ conf,    // [B]
    const int*   __restrict__ mask,    // [B,S]
    const int*   __restrict__ labels,  // [B,S]
    int S)
{
    constexpr int L = 128;
    extern __shared__ char sm[];
    // ebuf[group][phase][128] bf16  (group stride 512B, phase stride 256B)
    char*  ebuf  = sm;                                  // 1024B
    int*   smask = (int*)(sm + 1024);                   // [2][S]
    float* sred  = (float*)(sm + 1024 + 2 * S * 4);     // [2][8] scratch

    const int tid = threadIdx.x;
    const int g   = tid >> 7;          // batch group 0/1
    const int c   = tid & 127;         // owned column
    const int wg  = (tid >> 5) & 3;    // warp within group (0..3)
    const int b   = 2 * blockIdx.x + g;

    const float* fb = feats + (size_t)b * S * L;
    char* gbuf = ebuf + g * 512;       // this group's two phases

    // ---- expT column c into registers: 64 bf16x2 (i-pairs) ----
    __nv_bfloat162 T[64];
    #pragma unroll
    for (int k = 0; k < 64; ++k) {
        float t0 = __expf(__ldg(trans + (size_t)(2 * k) * L + c));
        float t1 = __expf(__ldg(trans + (size_t)(2 * k + 1) * L + c));
        T[k] = __floats2bfloat162_rn(t0, t1);
    }
    for (int k = c; k < S; k += 128) smask[g * S + k] = mask[b * S + k];

    // ---- alpha0: group max over 128 threads (4 warps) ----
    float a0 = startT[c] + fb[c];
    __syncthreads();                       // smask ready
    float mv = a0;
    #pragma unroll
    for (int o = 16; o; o >>= 1) mv = fmaxf(mv, __shfl_xor_sync(FULLMASK, mv, o));
    if ((tid & 31) == 0) sred[4 * g + wg] = mv;
    __syncthreads();
    float m0 = fmaxf(fmaxf(sred[4 * g], sred[4 * g + 1]),
                     fmaxf(sred[4 * g + 2], sred[4 * g + 3]));
    __syncthreads();

    float v = __expf(a0 - m0);             // exp-domain alpha, normalized
    float offset = m0;                     // alpha = offset + log(v)
    *(__nv_bfloat16*)(gbuf + 256 + 2 * c) = __float2bfloat16(v);  // phase 1

    float fA = fb[L + c];                              // feat(t=1)
    float fB = (S > 2) ? fb[2 * (size_t)L + c] : 0.f;  // feat(t=2)
    __syncthreads();

    const __nv_bfloat162 bz = __floats2bfloat162_rn(0.f, 0.f);

    for (int t = 1; t < S; ++t) {
        const uint4* se = (const uint4*)(gbuf + (t & 1) * 256);   // read phase
        char*        wb = gbuf + ((t & 1) ^ 1) * 256;             // write phase

        __nv_bfloat162 acc0 = bz, acc1 = bz, acc2 = bz, acc3 = bz;
        float e0f = 1.0f;
        #pragma unroll
        for (int p = 0; p < 16; ++p) {
            uint4 q = se[p];                       // e[8p .. 8p+7]
            __nv_bfloat162 q0 = *(__nv_bfloat162*)&q.x;
            __nv_bfloat162 q1 = *(__nv_bfloat162*)&q.y;
            __nv_bfloat162 q2 = *(__nv_bfloat162*)&q.z;
            __nv_bfloat162 q3 = *(__nv_bfloat162*)&q.w;
            if (p == 0) e0f = __low2float(q0);     // e[0]: free normalizer
            acc0 = __hfma2(q0, T[4 * p + 0], acc0);
            acc1 = __hfma2(q1, T[4 * p + 1], acc1);
            acc2 = __hfma2(q2, T[4 * p + 2], acc2);
            acc3 = __hfma2(q3, T[4 * p + 3], acc3);
        }
        acc0 = __hadd2(acc0, acc1);
        acc2 = __hadd2(acc2, acc3);
        acc0 = __hadd2(acc0, acc2);
        float s = __low2float(acc0) + __high2float(acc0);

        float fcur = fA;
        fA = fB;
        if (t + 2 < S) fB = fb[(size_t)(t + 2) * L + c];   // prefetch

        if (smask[g * S + t]) {
            v = s * __expf(fcur);
            if ((t & 3) == 0) {   // uniform rescale by e[0], exactly accounted
                v *= __frcp_rn(e0f);
                offset += __logf(e0f);
            }
        }
        // else masked: alpha (v) carries over unchanged

        *(__nv_bfloat16*)(wb + 2 * c) = __float2bfloat16(v);
        __syncthreads();
    }

    // ---- denominator: group sum over 128 threads ----
    float contrib = v * __expf(endT[c]);
    #pragma unroll
    for (int o = 16; o; o >>= 1) contrib += __shfl_xor_sync(FULLMASK, contrib, o);
    if ((tid & 31) == 0) sred[4 * g + wg] = contrib;
    __syncthreads();
    float log_den = offset + __logf((sred[4 * g] + sred[4 * g + 1])
                                  + (sred[4 * g + 2] + sred[4 * g + 3]));
    __syncthreads();

    // ---- numerator: label-path score (exact fp32) ----
    float num = 0.f;
    float slf = 0.f;
    const int* lb = labels + b * S;
    for (int k = c; k < S; k += 128) {
        int mk = smask[g * S + k];
        slf += (float)mk;
        int lab = lb[k]; if (lab == -100) lab = 0;
        if (k == 0) {
            num += startT[lab] + fb[lab];
        } else if (mk) {
            int lp = lb[k - 1]; if (lp == -100) lp = 0;
            num += trans[lp * L + lab] + fb[(size_t)k * L + lab];
        }
    }
    #pragma unroll
    for (int o = 16; o; o >>= 1) {
        num += __shfl_xor_sync(FULLMASK, num, o);
        slf += __shfl_xor_sync(FULLMASK, slf, o);
    }
    if ((tid & 31) == 0) { sred[4 * g + wg] = num; sred[8 + 4 * g + wg] = slf; }
    __syncthreads();
    num = (sred[4 * g] + sred[4 * g + 1]) + (sred[4 * g + 2] + sred[4 * g + 3]);
    slf = (sred[8 + 4 * g] + sred[8 + 4 * g + 1])
        + (sred[8 + 4 * g + 2] + sred[8 + 4 * g + 3]);

    int lastt = (int)(slf + 0.5f) - 1;
    if (lastt < 0) lastt = 0;
    int lastlab = lb[lastt]; if (lastlab == -100) lastlab = 0;
    num += endT[lastlab];

    if (c == 0) g_losses[b] = (log_den - num) * conf[b];
}

__global__ void k_finalize(float* __restrict__ out, int B) {
    int t = threadIdx.x;
    float x = (t < B) ? g_losses[t] : 0.f;
    #pragma unroll
    for (int o = 16; o; o >>= 1) x += __shfl_xor_sync(FULLMASK, x, o);
    __shared__ float sh[8];
    if ((t & 31) == 0) sh[t >> 5] = x;
    __syncthreads();
    if (t == 0) {
        float s = 0.f;
        int nw = (blockDim.x + 31) >> 5;
        for (int w = 0; w < nw; ++w) s += sh[w];
        out[0] = s / (float)B;
    }
}

extern "C" void kernel_launch(void* const* d_in, const int* in_sizes, int n_in,
                              void* d_out, int out_size) {
    const float* feats  = (const float*)d_in[0];
    const float* startT = (const float*)d_in[1];
    const float* endT   = (const float*)d_in[2];
    const float* trans  = (const float*)d_in[3];
    const float* conf   = (const float*)d_in[4];
    const int*   mask   = (const int*)  d_in[5];
    const int*   labels = (const int*)  d_in[6];

    const int B = in_sizes[4];            // 256
    const int S = in_sizes[5] / B;        // 512
    (void)n_in; (void)out_size;

    size_t smem = 1024                    // 2 groups x double-buffered e vecs
                + (size_t)2 * S * 4       // masks for both batches
                + 64;                     // reduction scratch

    k_crf_forward<<<B / 2, 256, smem>>>(feats, startT, endT, trans, conf,
                                        mask, labels, S);
    k_finalize<<<1, 256>>>((float*)d_out, B);
}

// round 8
// speedup vs baseline: 1.1097x; 1.1097x over previous
#include <cuda_runtime.h>
#include <cuda_bf16.h>

#define FULLMASK 0xffffffffu

__device__ float g_losses[256];

// Group-scoped barrier: group g (128 threads) syncs on named barrier g+1.
__device__ __forceinline__ void gbar(int g) {
    asm volatile("bar.sync %0, %1;" :: "r"(g + 1), "r"(128) : "memory");
}

// One CTA = 256 threads = 8 warps = TWO independent batch-groups:
//   warps 0-3 (SMSP 0-3) -> batch 2*bid, warps 4-7 (SMSP 0-3) -> batch 2*bid+1.
// Each group syncs on its OWN named barrier so the two warps sharing an SMSP
// (one per group) drift out of phase and hide each other's serial tails.
// Grid 128, occupancy 1: uniform 2 warps/SMSP chip-wide.
// Thread owns ONE column c: 64 bf16x2 expT regs, 64 HFMA2/step.
__global__ void __launch_bounds__(256, 1) k_crf_forward(
    const float* __restrict__ feats,   // [B,S,L]
    const float* __restrict__ startT,  // [L]
    const float* __restrict__ endT,    // [L]
    const float* __restrict__ trans,   // [L,L]
    const float* __restrict__ conf,    // [B]
    const int*   __restrict__ mask,    // [B,S]
    const int*   __restrict__ labels,  // [B,S]
    int S)
{
    constexpr int L = 128;
    extern __shared__ char sm[];
    // ebuf[group][phase][128] bf16  (group stride 512B, phase stride 256B)
    char*  ebuf  = sm;                                  // 1024B
    int*   smask = (int*)(sm + 1024);                   // [2][S]
    float* sred  = (float*)(sm + 1024 + 2 * S * 4);     // [2][8] scratch

    const int tid = threadIdx.x;
    const int g   = tid >> 7;          // batch group 0/1
    const int c   = tid & 127;         // owned column
    const int wg  = (tid >> 5) & 3;    // warp within group (0..3)
    const int b   = 2 * blockIdx.x + g;

    const float* fb = feats + (size_t)b * S * L;
    char* gbuf = ebuf + g * 512;       // this group's two phases

    // ---- expT column c into registers: 64 bf16x2 (i-pairs) ----
    __nv_bfloat162 T[64];
    #pragma unroll
    for (int k = 0; k < 64; ++k) {
        float t0 = __expf(__ldg(trans + (size_t)(2 * k) * L + c));
        float t1 = __expf(__ldg(trans + (size_t)(2 * k + 1) * L + c));
        T[k] = __floats2bfloat162_rn(t0, t1);
    }
    for (int k = c; k < S; k += 128) smask[g * S + k] = mask[b * S + k];

    // ---- alpha0: group max over 128 threads (4 warps) ----
    float a0 = startT[c] + fb[c];
    gbar(g);                               // group's smask ready
    float mv = a0;
    #pragma unroll
    for (int o = 16; o; o >>= 1) mv = fmaxf(mv, __shfl_xor_sync(FULLMASK, mv, o));
    if ((tid & 31) == 0) sred[4 * g + wg] = mv;
    gbar(g);
    float m0 = fmaxf(fmaxf(sred[4 * g], sred[4 * g + 1]),
                     fmaxf(sred[4 * g + 2], sred[4 * g + 3]));

    float v = __expf(a0 - m0);             // exp-domain alpha, normalized
    float offset = m0;                     // alpha = offset + log(v)
    *(__nv_bfloat16*)(gbuf + 256 + 2 * c) = __float2bfloat16(v);  // phase 1

    float fA = fb[L + c];                              // feat(t=1)
    float fB = (S > 2) ? fb[2 * (size_t)L + c] : 0.f;  // feat(t=2)
    gbar(g);

    const __nv_bfloat162 bz = __floats2bfloat162_rn(0.f, 0.f);

    for (int t = 1; t < S; ++t) {
        const uint4* se = (const uint4*)(gbuf + (t & 1) * 256);   // read phase
        char*        wb = gbuf + ((t & 1) ^ 1) * 256;             // write phase

        __nv_bfloat162 acc0 = bz, acc1 = bz, acc2 = bz, acc3 = bz;
        float e0f = 1.0f;
        #pragma unroll
        for (int p = 0; p < 16; ++p) {
            uint4 q = se[p];                       // e[8p .. 8p+7]
            __nv_bfloat162 q0 = *(__nv_bfloat162*)&q.x;
            __nv_bfloat162 q1 = *(__nv_bfloat162*)&q.y;
            __nv_bfloat162 q2 = *(__nv_bfloat162*)&q.z;
            __nv_bfloat162 q3 = *(__nv_bfloat162*)&q.w;
            if (p == 0) e0f = __low2float(q0);     // e[0]: free normalizer
            acc0 = __hfma2(q0, T[4 * p + 0], acc0);
            acc1 = __hfma2(q1, T[4 * p + 1], acc1);
            acc2 = __hfma2(q2, T[4 * p + 2], acc2);
            acc3 = __hfma2(q3, T[4 * p + 3], acc3);
        }
        acc0 = __hadd2(acc0, acc1);
        acc2 = __hadd2(acc2, acc3);
        acc0 = __hadd2(acc0, acc2);
        float s = __low2float(acc0) + __high2float(acc0);

        float fcur = fA;
        fA = fB;
        if (t + 2 < S) fB = fb[(size_t)(t + 2) * L + c];   // prefetch

        if (smask[g * S + t]) {
            v = s * __expf(fcur);
            if ((t & 3) == 0) {   // uniform rescale by e[0], exactly accounted
                v *= __frcp_rn(e0f);
                offset += __logf(e0f);
            }
        }
        // else masked: alpha (v) carries over unchanged

        *(__nv_bfloat16*)(wb + 2 * c) = __float2bfloat16(v);
        gbar(g);
    }

    // ---- denominator: group sum over 128 threads ----
    float contrib = v * __expf(endT[c]);
    #pragma unroll
    for (int o = 16; o; o >>= 1) contrib += __shfl_xor_sync(FULLMASK, contrib, o);
    if ((tid & 31) == 0) sred[4 * g + wg] = contrib;
    gbar(g);
    float log_den = offset + __logf((sred[4 * g] + sred[4 * g + 1])
                                  + (sred[4 * g + 2] + sred[4 * g + 3]));
    gbar(g);

    // ---- numerator: label-path score (exact fp32) ----
    float num = 0.f;
    float slf = 0.f;
    const int* lb = labels + b * S;
    for (int k = c; k < S; k += 128) {
        int mk = smask[g * S + k];
        slf += (float)mk;
        int lab = lb[k]; if (lab == -100) lab = 0;
        if (k == 0) {
            num += startT[lab] + fb[lab];
        } else if (mk) {
            int lp = lb[k - 1]; if (lp == -100) lp = 0;
            num += trans[lp * L + lab] + fb[(size_t)k * L + lab];
        }
    }
    #pragma unroll
    for (int o = 16; o; o >>= 1) {
        num += __shfl_xor_sync(FULLMASK, num, o);
        slf += __shfl_xor_sync(FULLMASK, slf, o);
    }
    if ((tid & 31) == 0) { sred[4 * g + wg] = num; sred[8 + 4 * g + wg] = slf; }
    gbar(g);
    num = (sred[4 * g] + sred[4 * g + 1]) + (sred[4 * g + 2] + sred[4 * g + 3]);
    slf = (sred[8 + 4 * g] + sred[8 + 4 * g + 1])
        + (sred[8 + 4 * g + 2] + sred[8 + 4 * g + 3]);

    int lastt = (int)(slf + 0.5f) - 1;
    if (lastt < 0) lastt = 0;
    int lastlab = lb[lastt]; if (lastlab == -100) lastlab = 0;
    num += endT[lastlab];

    if (c == 0) g_losses[b] = (log_den - num) * conf[b];
}

__global__ void k_finalize(float* __restrict__ out, int B) {
    int t = threadIdx.x;
    float x = (t < B) ? g_losses[t] : 0.f;
    #pragma unroll
    for (int o = 16; o; o >>= 1) x += __shfl_xor_sync(FULLMASK, x, o);
    __shared__ float sh[8];
    if ((t & 31) == 0) sh[t >> 5] = x;
    __syncthreads();
    if (t == 0) {
        float s = 0.f;
        int nw = (blockDim.x + 31) >> 5;
        for (int w = 0; w < nw; ++w) s += sh[w];
        out[0] = s / (float)B;
    }
}

extern "C" void kernel_launch(void* const* d_in, const int* in_sizes, int n_in,
                              void* d_out, int out_size) {
    const float* feats  = (const float*)d_in[0];
    const float* startT = (const float*)d_in[1];
    const float* endT   = (const float*)d_in[2];
    const float* trans  = (const float*)d_in[3];
    const float* conf   = (const float*)d_in[4];
    const int*   mask   = (const int*)  d_in[5];
    const int*   labels = (const int*)  d_in[6];

    const int B = in_sizes[4];            // 256
    const int S = in_sizes[5] / B;        // 512
    (void)n_in; (void)out_size;

    size_t smem = 1024                    // 2 groups x double-buffered e vecs
                + (size_t)2 * S * 4       // masks for both batches
                + 64;                     // reduction scratch

    k_crf_forward<<<B / 2, 256, smem>>>(feats, startT, endT, trans, conf,
                                        mask, labels, S);
    k_finalize<<<1, 256>>>((float*)d_out, B);
}